// round 12
// baseline (speedup 1.0000x reference)
#include <cuda_runtime.h>

#define NQ 1024
#define NK 2048
#define D  64
typedef unsigned long long ull;

__device__ float g_qp [NQ * D];
__device__ float g_kpb[NK * D];
__device__ float g_vt [NK * D];
__device__ float g_sep[NQ * 32];
__device__ unsigned g_launch;
__device__ unsigned g_fqc[16], g_fkc[32];

__device__ __forceinline__ unsigned ldacq(const unsigned* p) {
    unsigned v; asm volatile("ld.acquire.gpu.global.u32 %0, [%1];" : "=r"(v) : "l"(p)); return v;
}
__device__ __forceinline__ void relinc(unsigned* p) {
    asm volatile("red.release.gpu.global.add.u32 [%0], 1;" :: "l"(p));
}
__device__ __forceinline__ unsigned su32(const void* p) {
    return (unsigned)__cvta_generic_to_shared(p);
}
#define CPA16(dst, src) asm volatile("cp.async.ca.shared.global [%0], [%1], 16;" :: "r"(dst), "l"(src))
#define CPCOMMIT() asm volatile("cp.async.commit_group;")
#define CPWAIT() asm volatile("cp.async.wait_group 0;")
#define FMA2(acc, a, b) asm("fma.rn.f32x2 %0, %1, %2, %0;" : "+l"(acc) : "l"(a), "l"(b))
#define RELU_FMA2(acc, a, b, w) asm("{\n\t.reg .b64 t;\n\t.reg .f32 lo, hi;\n\t" \
    "add.rn.f32x2 t, %1, %2;\n\tmov.b64 {lo, hi}, t;\n\t"                        \
    "max.f32 lo, lo, 0f00000000;\n\tmax.f32 hi, hi, 0f00000000;\n\t"             \
    "mov.b64 t, {lo, hi};\n\tfma.rn.f32x2 %0, %3, t, %0;\n\t}"                   \
    : "+l"(acc) : "l"(a), "l"(b), "l"(w))

// ---- Kernel A: proj/transpose producers + scores consumers (unchanged). ----
__global__ void __launch_bounds__(256, 3)
k_scores(const float* __restrict__ query, const float* __restrict__ key,
         const float* __restrict__ value, const float* __restrict__ W1,
         const float* __restrict__ b1, const float* __restrict__ W2,
         const float* __restrict__ b2, float* __restrict__ out,
         float* __restrict__ scores)
{
    __shared__ float qs[64][66];
    __shared__ float ks[64][66];
    __shared__ ull w2s[32];
    __shared__ unsigned s_call;

    int tid = threadIdx.x;
    int qt = blockIdx.x, kt = blockIdx.y;
    int lin = kt * 16 + qt;

    if (tid == 0) {
        unsigned my; asm volatile("atom.relaxed.gpu.global.add.u32 %0, [%1], 1;" : "=r"(my) : "l"(&g_launch));
        s_call = my / 512;
    }
    __syncthreads();
    unsigned call = s_call;

    if (lin < 192) {
        float (*Ws)[66] = (float (*)[66])qs;
        float (*Xs)[16] = (float (*)[16])ks;
        bool isQ = (lin < 64);
        int c0 = (isQ ? lin : (lin - 64)) * 16;
        const float* src = isQ ? query : key;
        int stride = isQ ? NQ : NK;
        int wofs = isQ ? 0 : D;
        {
            int h = tid >> 2, ds = (tid & 3) * 16;
            const float* wr = W1 + h * (2 * D) + wofs + ds;
            #pragma unroll
            for (int j = 0; j < 4; j++) {
                float4 v = *(const float4*)(wr + 4 * j);
                Ws[ds + 4*j + 0][h] = v.x; Ws[ds + 4*j + 1][h] = v.y;
                Ws[ds + 4*j + 2][h] = v.z; Ws[ds + 4*j + 3][h] = v.w;
            }
        }
        {
            int d = tid >> 2, c = (tid & 3) * 4;
            *(float4*)&Xs[d][c] = *(const float4*)&src[d * stride + c0 + c];
        }
        __syncthreads();
        int h = tid & 63, cg = tid >> 6;
        float bias = isQ ? 0.0f : b1[h];
        float a0 = bias, a1 = bias, a2 = bias, a3 = bias;
        #pragma unroll 16
        for (int d = 0; d < D; d++) {
            float w = Ws[d][h];
            float4 x = *(float4*)&Xs[d][cg * 4];
            a0 += w * x.x; a1 += w * x.y; a2 += w * x.z; a3 += w * x.w;
        }
        float* dst = (isQ ? g_qp : g_kpb) + (c0 + cg * 4) * D + h;
        dst[0] = a0; dst[D] = a1; dst[2 * D] = a2; dst[3 * D] = a3;

        __threadfence();
        __syncthreads();
        if (tid == 0) relinc(isQ ? &g_fqc[lin >> 2] : &g_fkc[(lin - 64) >> 2]);
        __syncthreads();
    } else if (lin < 320) {
        float (*tile)[33] = (float (*)[33])qs;
        int tv = lin - 192;
        if (tv < 16) {
            #pragma unroll
            for (int j = 0; j < 4; j++)
                *(float4*)&out[tv * 4096 + j * 1024 + tid * 4] = make_float4(0.f,0.f,0.f,0.f);
        }
        int k0 = (tv >> 1) * 32, d0 = (tv & 1) * 32;
        int tx = tid & 31, ty = tid >> 5;
        #pragma unroll
        for (int r = 0; r < 32; r += 8)
            tile[ty + r][tx] = value[(d0 + ty + r) * NK + k0 + tx];
        __syncthreads();
        #pragma unroll
        for (int r = 0; r < 32; r += 8)
            g_vt[(k0 + ty + r) * D + d0 + tx] = tile[tx][ty + r];
        __syncthreads();
    }

    if (tid == 0) {
        unsigned tgt = 4 * (call + 1);
        while (ldacq(&g_fqc[qt]) < tgt) __nanosleep(32);
        while (ldacq(&g_fkc[kt]) < tgt) __nanosleep(32);
    }
    __syncthreads();

    int qbase = qt * 64, kbase = kt * 64;
    for (int i = tid; i < 64 * 32; i += 256) {
        int r = i >> 5, c = (i & 31) * 2;
        *(float2*)&qs[r][c] = *(const float2*)&g_qp [(qbase + r) * D + c];
        *(float2*)&ks[r][c] = *(const float2*)&g_kpb[(kbase + r) * D + c];
    }
    if (tid < 32) {
        float2 w = *(const float2*)&W2[2 * tid];
        ull p; asm("mov.b64 %0, {%1,%2};" : "=l"(p) : "f"(w.x), "f"(w.y));
        w2s[tid] = p;
    }
    __syncthreads();

    int tx = tid & 15, ty = tid >> 4;
    ull acc[4][4];
    #pragma unroll
    for (int i = 0; i < 4; i++)
        #pragma unroll
        for (int j = 0; j < 4; j++) acc[i][j] = 0ull;

    #pragma unroll 4
    for (int h = 0; h < 64; h += 2) {
        ull w2 = w2s[h >> 1];
        ull a[4], bb[4];
        #pragma unroll
        for (int i = 0; i < 4; i++) a[i]  = *(ull*)&qs[ty + 16 * i][h];
        #pragma unroll
        for (int j = 0; j < 4; j++) bb[j] = *(ull*)&ks[tx + 16 * j][h];
        #pragma unroll
        for (int i = 0; i < 4; i++)
            #pragma unroll
            for (int j = 0; j < 4; j++)
                RELU_FMA2(acc[i][j], a[i], bb[j], w2);
    }

    float bias = b2[0];
    #pragma unroll
    for (int i = 0; i < 4; i++) {
        int q = qbase + ty + 16 * i;
        float rsum = 0.0f;
        #pragma unroll
        for (int j = 0; j < 4; j++) {
            float lo, hi;
            asm("mov.b64 {%0,%1}, %2;" : "=f"(lo), "=f"(hi) : "l"(acc[i][j]));
            float s = lo + hi + bias;
            scores[q * NK + kbase + tx + 16 * j] = s;
            rsum += __expf(s);
        }
        #pragma unroll
        for (int o = 8; o > 0; o >>= 1)
            rsum += __shfl_xor_sync(~0u, rsum, o);
        if (tx == 0) g_sep[q * 32 + kt] = rsum;
    }
}

// ---- Kernel B: out[d][q] += sum_k exp(s)/Z * vt[k][d].
// 128 blocks x 512 thr: q-tile 16, k-split 2 (1024 k each). One wave. ----
__global__ void __launch_bounds__(512, 1) k_pv(const float* __restrict__ scores,
                                               float* __restrict__ out)
{
    __shared__ float vs[2][64][68];     // 34816 B
    __shared__ float ps[2][64][20];     // 10240 B

    int q0 = (blockIdx.x >> 1) * 16;
    int kb0 = (blockIdx.x & 1) * (NK / 2);
    int tid = threadIdx.x, w = tid >> 5, lane = tid & 31;

    // p staging: sq = warp (const per warp), skk = lane; 2 kk per thread
    int sq = tid >> 5, skk = tid & 31;
    float se = 0.0f;
    {
        const float* sep = g_sep + (q0 + sq) * 32;
        #pragma unroll
        for (int j = 0; j < 32; j += 4) {
            float4 v = *(const float4*)(sep + j);
            se += (v.x + v.y) + (v.z + v.w);
        }
    }
    float ri = 1.0f / se;
    const float* srow = scores + (q0 + sq) * NK + kb0 + skk;

    // v staging: 64 rows x 16 float4 = 1024 float4 / 512 thr = 2 each
    int vk = tid >> 3, vh = (tid & 7) * 8;
    {
        const float* src = g_vt + (kb0 + vk) * D + vh;
        unsigned dst = su32(&vs[0][vk][vh]);
        CPA16(dst, src); CPA16(dst + 16, src + 4);
        CPCOMMIT();
    }
    float sc0 = srow[0], sc1 = srow[32];

    ull accx[8] = {0,0,0,0,0,0,0,0};
    ull accy[8] = {0,0,0,0,0,0,0,0};

    for (int t = 0; t < 16; t++) {
        int buf = t & 1;
        CPWAIT();
        __syncthreads();
        ps[buf][skk     ][sq] = __expf(sc0) * ri;
        ps[buf][skk + 32][sq] = __expf(sc1) * ri;
        if (t < 15) {
            const float* src = g_vt + (kb0 + (t + 1) * 64 + vk) * D + vh;
            unsigned dst = su32(&vs[buf ^ 1][vk][vh]);
            CPA16(dst, src); CPA16(dst + 16, src + 4);
            CPCOMMIT();
            sc0 = srow[(t + 1) * 64];
            sc1 = srow[(t + 1) * 64 + 32];
        }
        __syncthreads();

        int kb = w * 4;                 // 16 warps x 4 kk
        #pragma unroll
        for (int u = 0; u < 4; u++) {
            int kk = kb + u;
            float2 v = *(float2*)&vs[buf][kk][2 * lane];
            ulonglong2 pA = *(ulonglong2*)&ps[buf][kk][0];
            ulonglong2 pB = *(ulonglong2*)&ps[buf][kk][4];
            ulonglong2 pC = *(ulonglong2*)&ps[buf][kk][8];
            ulonglong2 pD = *(ulonglong2*)&ps[buf][kk][12];
            ull vx, vy;
            asm("mov.b64 %0, {%1,%1};" : "=l"(vx) : "f"(v.x));
            asm("mov.b64 %0, {%1,%1};" : "=l"(vy) : "f"(v.y));
            FMA2(accx[0], pA.x, vx); FMA2(accx[1], pA.y, vx);
            FMA2(accx[2], pB.x, vx); FMA2(accx[3], pB.y, vx);
            FMA2(accx[4], pC.x, vx); FMA2(accx[5], pC.y, vx);
            FMA2(accx[6], pD.x, vx); FMA2(accx[7], pD.y, vx);
            FMA2(accy[0], pA.x, vy); FMA2(accy[1], pA.y, vy);
            FMA2(accy[2], pB.x, vy); FMA2(accy[3], pB.y, vy);
            FMA2(accy[4], pC.x, vy); FMA2(accy[5], pC.y, vy);
            FMA2(accy[6], pD.x, vy); FMA2(accy[7], pD.y, vy);
        }
    }

    // two-stage cross-warp reduction (16 warps -> 8 rows -> final)
    __syncthreads();
    float* red = (float*)vs;            // 32 KB of the 34.8 KB vs pool
    int w8 = w & 7;
    int base = (w8 * 32 + lane) * 32;
    if (w < 8) {
        #pragma unroll
        for (int jp = 0; jp < 8; jp++) {
            float lo, hi;
            asm("mov.b64 {%0,%1}, %2;" : "=f"(lo), "=f"(hi) : "l"(accx[jp]));
            red[base + 2 * jp] = lo; red[base + 2 * jp + 1] = hi;
            asm("mov.b64 {%0,%1}, %2;" : "=f"(lo), "=f"(hi) : "l"(accy[jp]));
            red[base + 16 + 2 * jp] = lo; red[base + 16 + 2 * jp + 1] = hi;
        }
    }
    __syncthreads();
    if (w >= 8) {
        #pragma unroll
        for (int jp = 0; jp < 8; jp++) {
            float lo, hi;
            asm("mov.b64 {%0,%1}, %2;" : "=f"(lo), "=f"(hi) : "l"(accx[jp]));
            red[base + 2 * jp] += lo; red[base + 2 * jp + 1] += hi;
            asm("mov.b64 {%0,%1}, %2;" : "=f"(lo), "=f"(hi) : "l"(accy[jp]));
            red[base + 16 + 2 * jp] += lo; red[base + 16 + 2 * jp + 1] += hi;
        }
    }
    __syncthreads();

    #pragma unroll
    for (int r = tid; r < 1024; r += 512) {
        int d = r >> 4, q = r & 15;
        int ln = d >> 1, sel = (d & 1) * 16 + q;
        float s = 0.0f;
        #pragma unroll
        for (int ww = 0; ww < 8; ww++) s += red[(ww * 32 + ln) * 32 + sel];
        atomicAdd(&out[d * NQ + q0 + q], s);
    }
}

// ---------------------------------------------------------------------------
extern "C" void kernel_launch(void* const* d_in, const int* in_sizes, int n_in,
                              void* d_out, int out_size)
{
    const float* query = (const float*)d_in[0];
    const float* key   = (const float*)d_in[1];
    const float* value = (const float*)d_in[2];
    const float* W1    = (const float*)d_in[3];
    const float* b1    = (const float*)d_in[4];
    const float* W2    = (const float*)d_in[5];
    const float* b2    = (const float*)d_in[6];

    float* out_p    = (float*)d_out;
    float* scores_p = (float*)d_out + NQ * D;

    k_scores<<<dim3(16, 32), 256>>>(query, key, value, W1, b1, W2, b2, out_p, scores_p);
    k_pv<<<128, 512>>>(scores_p, out_p);
}

// round 13
// speedup vs baseline: 1.1341x; 1.1341x over previous
#include <cuda_runtime.h>

#define NQ 1024
#define NK 2048
#define D  64
typedef unsigned long long ull;

__device__ float g_qp [NQ * D];
__device__ float g_kpb[NK * D];
__device__ float g_vt [NK * D];
__device__ float g_sep[NQ * 32];
__device__ unsigned g_launch;
__device__ unsigned g_fqc[16], g_fkc[32];

__device__ __forceinline__ unsigned ldacq(const unsigned* p) {
    unsigned v; asm volatile("ld.acquire.gpu.global.u32 %0, [%1];" : "=r"(v) : "l"(p)); return v;
}
__device__ __forceinline__ void relinc(unsigned* p) {
    asm volatile("red.release.gpu.global.add.u32 [%0], 1;" :: "l"(p));
}
__device__ __forceinline__ unsigned su32(const void* p) {
    return (unsigned)__cvta_generic_to_shared(p);
}
#define CPA16(dst, src) asm volatile("cp.async.ca.shared.global [%0], [%1], 16;" :: "r"(dst), "l"(src))
#define CPCOMMIT() asm volatile("cp.async.commit_group;")
#define CPWAIT() asm volatile("cp.async.wait_group 0;")
#define FMA2(acc, a, b) asm("fma.rn.f32x2 %0, %1, %2, %0;" : "+l"(acc) : "l"(a), "l"(b))
#define RELU_FMA2(acc, a, b, w) asm("{\n\t.reg .b64 t;\n\t.reg .f32 lo, hi;\n\t" \
    "add.rn.f32x2 t, %1, %2;\n\tmov.b64 {lo, hi}, t;\n\t"                        \
    "max.f32 lo, lo, 0f00000000;\n\tmax.f32 hi, hi, 0f00000000;\n\t"             \
    "mov.b64 t, {lo, hi};\n\tfma.rn.f32x2 %0, %3, t, %0;\n\t}"                   \
    : "+l"(acc) : "l"(a), "l"(b), "l"(w))

// ---- Kernel A: proj/transpose producers + scores consumers (unchanged). ----
__global__ void __launch_bounds__(256, 3)
k_scores(const float* __restrict__ query, const float* __restrict__ key,
         const float* __restrict__ value, const float* __restrict__ W1,
         const float* __restrict__ b1, const float* __restrict__ W2,
         const float* __restrict__ b2, float* __restrict__ out,
         float* __restrict__ scores)
{
    __shared__ float qs[64][66];
    __shared__ float ks[64][66];
    __shared__ ull w2s[32];
    __shared__ unsigned s_call;

    int tid = threadIdx.x;
    int qt = blockIdx.x, kt = blockIdx.y;
    int lin = kt * 16 + qt;

    if (tid == 0) {
        unsigned my; asm volatile("atom.relaxed.gpu.global.add.u32 %0, [%1], 1;" : "=r"(my) : "l"(&g_launch));
        s_call = my / 512;
    }
    __syncthreads();
    unsigned call = s_call;

    if (lin < 192) {
        float (*Ws)[66] = (float (*)[66])qs;
        float (*Xs)[16] = (float (*)[16])ks;
        bool isQ = (lin < 64);
        int c0 = (isQ ? lin : (lin - 64)) * 16;
        const float* src = isQ ? query : key;
        int stride = isQ ? NQ : NK;
        int wofs = isQ ? 0 : D;
        {
            int h = tid >> 2, ds = (tid & 3) * 16;
            const float* wr = W1 + h * (2 * D) + wofs + ds;
            #pragma unroll
            for (int j = 0; j < 4; j++) {
                float4 v = *(const float4*)(wr + 4 * j);
                Ws[ds + 4*j + 0][h] = v.x; Ws[ds + 4*j + 1][h] = v.y;
                Ws[ds + 4*j + 2][h] = v.z; Ws[ds + 4*j + 3][h] = v.w;
            }
        }
        {
            int d = tid >> 2, c = (tid & 3) * 4;
            *(float4*)&Xs[d][c] = *(const float4*)&src[d * stride + c0 + c];
        }
        __syncthreads();
        int h = tid & 63, cg = tid >> 6;
        float bias = isQ ? 0.0f : b1[h];
        float a0 = bias, a1 = bias, a2 = bias, a3 = bias;
        #pragma unroll 16
        for (int d = 0; d < D; d++) {
            float w = Ws[d][h];
            float4 x = *(float4*)&Xs[d][cg * 4];
            a0 += w * x.x; a1 += w * x.y; a2 += w * x.z; a3 += w * x.w;
        }
        float* dst = (isQ ? g_qp : g_kpb) + (c0 + cg * 4) * D + h;
        dst[0] = a0; dst[D] = a1; dst[2 * D] = a2; dst[3 * D] = a3;

        __threadfence();
        __syncthreads();
        if (tid == 0) relinc(isQ ? &g_fqc[lin >> 2] : &g_fkc[(lin - 64) >> 2]);
        __syncthreads();
    } else if (lin < 320) {
        float (*tile)[33] = (float (*)[33])qs;
        int tv = lin - 192;
        if (tv < 16) {
            #pragma unroll
            for (int j = 0; j < 4; j++)
                *(float4*)&out[tv * 4096 + j * 1024 + tid * 4] = make_float4(0.f,0.f,0.f,0.f);
        }
        int k0 = (tv >> 1) * 32, d0 = (tv & 1) * 32;
        int tx = tid & 31, ty = tid >> 5;
        #pragma unroll
        for (int r = 0; r < 32; r += 8)
            tile[ty + r][tx] = value[(d0 + ty + r) * NK + k0 + tx];
        __syncthreads();
        #pragma unroll
        for (int r = 0; r < 32; r += 8)
            g_vt[(k0 + ty + r) * D + d0 + tx] = tile[tx][ty + r];
        __syncthreads();
    }

    if (tid == 0) {
        unsigned tgt = 4 * (call + 1);
        while (ldacq(&g_fqc[qt]) < tgt) __nanosleep(32);
        while (ldacq(&g_fkc[kt]) < tgt) __nanosleep(32);
    }
    __syncthreads();

    int qbase = qt * 64, kbase = kt * 64;
    for (int i = tid; i < 64 * 32; i += 256) {
        int r = i >> 5, c = (i & 31) * 2;
        *(float2*)&qs[r][c] = *(const float2*)&g_qp [(qbase + r) * D + c];
        *(float2*)&ks[r][c] = *(const float2*)&g_kpb[(kbase + r) * D + c];
    }
    if (tid < 32) {
        float2 w = *(const float2*)&W2[2 * tid];
        ull p; asm("mov.b64 %0, {%1,%2};" : "=l"(p) : "f"(w.x), "f"(w.y));
        w2s[tid] = p;
    }
    __syncthreads();

    int tx = tid & 15, ty = tid >> 4;
    ull acc[4][4];
    #pragma unroll
    for (int i = 0; i < 4; i++)
        #pragma unroll
        for (int j = 0; j < 4; j++) acc[i][j] = 0ull;

    #pragma unroll 4
    for (int h = 0; h < 64; h += 2) {
        ull w2 = w2s[h >> 1];
        ull a[4], bb[4];
        #pragma unroll
        for (int i = 0; i < 4; i++) a[i]  = *(ull*)&qs[ty + 16 * i][h];
        #pragma unroll
        for (int j = 0; j < 4; j++) bb[j] = *(ull*)&ks[tx + 16 * j][h];
        #pragma unroll
        for (int i = 0; i < 4; i++)
            #pragma unroll
            for (int j = 0; j < 4; j++)
                RELU_FMA2(acc[i][j], a[i], bb[j], w2);
    }

    float bias = b2[0];
    #pragma unroll
    for (int i = 0; i < 4; i++) {
        int q = qbase + ty + 16 * i;
        float rsum = 0.0f;
        #pragma unroll
        for (int j = 0; j < 4; j++) {
            float lo, hi;
            asm("mov.b64 {%0,%1}, %2;" : "=f"(lo), "=f"(hi) : "l"(acc[i][j]));
            float s = lo + hi + bias;
            scores[q * NK + kbase + tx + 16 * j] = s;
            rsum += __expf(s);
        }
        #pragma unroll
        for (int o = 8; o > 0; o >>= 1)
            rsum += __shfl_xor_sync(~0u, rsum, o);
        if (tx == 0) g_sep[q * 32 + kt] = rsum;
    }
}

// ---- Kernel B: out[d][q] += sum_k exp(s)/Z * vt[k][d].
// 256 blocks x 256 thr, q16 x ksplit4. Warp = (kslice, dhalf); thread owns
// 1 d x 16 q => 8 ull accs. 3 blocks/SM resident. ----
__global__ void __launch_bounds__(256, 3) k_pv(const float* __restrict__ scores,
                                               float* __restrict__ out)
{
    __shared__ float vs[2][64][68];     // 34816 B
    __shared__ float ps[2][64][20];     // 10240 B

    int q0 = (blockIdx.x >> 2) * 16;
    int kb0 = (blockIdx.x & 3) * (NK / 4);
    int tid = threadIdx.x, w = tid >> 5, lane = tid & 31;
    int ksl = w & 3, dhalf = w >> 2;    // warp role
    int myd = dhalf * 32 + lane;

    int skk = tid & 15, sq = tid >> 4;
    float se = 0.0f;
    {
        const float* sep = g_sep + (q0 + sq) * 32;
        #pragma unroll
        for (int j = 0; j < 32; j += 4) {
            float4 v = *(const float4*)(sep + j);
            se += (v.x + v.y) + (v.z + v.w);
        }
    }
    float ri = 1.0f / se;
    const float* srow = scores + (q0 + sq) * NK + kb0 + skk;

    int vk = tid >> 2, vh = (tid & 3) * 16;
    {
        const float* src = g_vt + (kb0 + vk) * D + vh;
        unsigned dst = su32(&vs[0][vk][vh]);
        #pragma unroll
        for (int j = 0; j < 4; j++) CPA16(dst + 16 * j, src + 4 * j);
        CPCOMMIT();
    }
    float sc[4];
    #pragma unroll
    for (int i = 0; i < 4; i++) sc[i] = srow[16 * i];

    ull acc[8] = {0,0,0,0,0,0,0,0};     // 16 q as 8 pairs, d = myd

    for (int t = 0; t < 8; t++) {       // 8 tiles of 64 k
        int buf = t & 1;
        CPWAIT();
        __syncthreads();
        #pragma unroll
        for (int i = 0; i < 4; i++)
            ps[buf][skk + 16 * i][sq] = __expf(sc[i]) * ri;
        if (t < 7) {
            const float* src = g_vt + (kb0 + (t + 1) * 64 + vk) * D + vh;
            unsigned dst = su32(&vs[buf ^ 1][vk][vh]);
            #pragma unroll
            for (int j = 0; j < 4; j++) CPA16(dst + 16 * j, src + 4 * j);
            CPCOMMIT();
            #pragma unroll
            for (int i = 0; i < 4; i++) sc[i] = srow[(t + 1) * 64 + 16 * i];
        }
        __syncthreads();

        int kb = ksl * 16;              // 16 kk per warp, d-half per warp
        #pragma unroll
        for (int u = 0; u < 16; u++) {
            int kk = kb + u;
            float v = vs[buf][kk][myd];
            ulonglong2 pA = *(ulonglong2*)&ps[buf][kk][0];
            ulonglong2 pB = *(ulonglong2*)&ps[buf][kk][4];
            ulonglong2 pC = *(ulonglong2*)&ps[buf][kk][8];
            ulonglong2 pD = *(ulonglong2*)&ps[buf][kk][12];
            ull vx;
            asm("mov.b64 %0, {%1,%1};" : "=l"(vx) : "f"(v));
            FMA2(acc[0], pA.x, vx); FMA2(acc[1], pA.y, vx);
            FMA2(acc[2], pB.x, vx); FMA2(acc[3], pB.y, vx);
            FMA2(acc[4], pC.x, vx); FMA2(acc[5], pC.y, vx);
            FMA2(acc[6], pD.x, vx); FMA2(acc[7], pD.y, vx);
        }
    }

    // reduction over 4 kslices per (d, q). red[w][lane][16 q]
    __syncthreads();
    float* red = (float*)vs;            // 16 KB of the 34.8 KB pool
    int base = (w * 32 + lane) * 16;
    #pragma unroll
    for (int jp = 0; jp < 8; jp++) {
        float lo, hi;
        asm("mov.b64 {%0,%1}, %2;" : "=f"(lo), "=f"(hi) : "l"(acc[jp]));
        red[base + 2 * jp] = lo; red[base + 2 * jp + 1] = hi;
    }
    __syncthreads();

    #pragma unroll
    for (int r = tid; r < 1024; r += 256) {
        int d = r >> 4, q = r & 15;
        int dh = d >> 5, ln = d & 31;
        float s = 0.0f;
        #pragma unroll
        for (int ks = 0; ks < 4; ks++)
            s += red[((dh * 4 + ks) * 32 + ln) * 16 + q];
        atomicAdd(&out[d * NQ + q0 + q], s);
    }
}

// ---------------------------------------------------------------------------
extern "C" void kernel_launch(void* const* d_in, const int* in_sizes, int n_in,
                              void* d_out, int out_size)
{
    const float* query = (const float*)d_in[0];
    const float* key   = (const float*)d_in[1];
    const float* value = (const float*)d_in[2];
    const float* W1    = (const float*)d_in[3];
    const float* b1    = (const float*)d_in[4];
    const float* W2    = (const float*)d_in[5];
    const float* b2    = (const float*)d_in[6];

    float* out_p    = (float*)d_out;
    float* scores_p = (float*)d_out + NQ * D;

    k_scores<<<dim3(16, 32), 256>>>(query, key, value, W1, b1, W2, b2, out_p, scores_p);
    k_pv<<<256, 256>>>(scores_p, out_p);
}